// round 10
// baseline (speedup 1.0000x reference)
#include <cuda_runtime.h>
#include <cfloat>

#define BB 256
#define TT 512
#define KK 128
#define TRP 132   // padded transposed-transitions row stride (floats)
#define PTR 132   // padded partials row stride (floats)

// Scratch (__device__ globals only — no runtime allocation)
__device__ float g_states[(size_t)BB * TT * KK];   // 64 MiB Viterbi states
__device__ int   g_order[BB];                      // bid -> batch (desc length)

// ---------------------------------------------------------------------------
// Rank batches by descending length; bid = rank (longest launch first; with
// 1 CTA/SM the 148 longest fill wave 1, shorter ones backfill as SMs free).
// ---------------------------------------------------------------------------
__global__ void order_kernel(const int* __restrict__ lens)
{
    __shared__ int sl[BB];
    const int b = threadIdx.x;
    sl[b] = lens[b];
    __syncthreads();
    const int L = sl[b];
    int r = 0;
    #pragma unroll 8
    for (int i = 0; i < BB; ++i) {
        int Li = sl[i];
        r += (Li > L) || (Li == L && i < b);
    }
    g_order[r] = b;
}

// ---------------------------------------------------------------------------
// Packed f32x2 add (sm_103a). max.f32x2 does not exist; FMNMX stays scalar.
// ---------------------------------------------------------------------------
__device__ __forceinline__ unsigned long long addx2(unsigned long long a,
                                                    unsigned long long b) {
    unsigned long long r;
    asm("add.rn.f32x2 %0, %1, %2;" : "=l"(r) : "l"(a), "l"(b));
    return r;
}
__device__ __forceinline__ float2 unpk(unsigned long long v) {
    float2 r;
    asm("mov.b64 {%0, %1}, %2;" : "=f"(r.x), "=f"(r.y) : "l"(v));
    return r;
}
__device__ __forceinline__ unsigned long long pk(float lo, float hi) {
    unsigned long long r;
    asm("mov.b64 %0, {%1, %2};" : "=l"(r) : "f"(lo), "f"(hi));
    return r;
}
__device__ __forceinline__ void bar_named(int id, int cnt) {
    asm volatile("bar.sync %0, %1;" :: "r"(id), "r"(cnt) : "memory");
}

// ---------------------------------------------------------------------------
// Backtrace helpers (warp-uniform argmax, first-index tie-break)
// ---------------------------------------------------------------------------
__device__ __forceinline__ unsigned redux_max_u32(unsigned v) {
    unsigned r;
    asm("redux.sync.max.u32 %0, %1, 0xffffffff;" : "=r"(r) : "r"(v));
    return r;
}
__device__ __forceinline__ unsigned redux_min_u32(unsigned v) {
    unsigned r;
    asm("redux.sync.min.u32 %0, %1, 0xffffffff;" : "=r"(r) : "r"(v));
    return r;
}
__device__ __forceinline__ unsigned fkey(float f) {
    unsigned u = __float_as_uint(f);
    return u ^ ((unsigned)((int)u >> 31) | 0x80000000u);
}
__device__ __forceinline__ int argmax128(float4 v, int l)
{
    unsigned k0 = fkey(v.x), k1 = fkey(v.y), k2 = fkey(v.z), k3 = fkey(v.w);
    unsigned km = max(max(k0, k1), max(k2, k3));
    unsigned M  = redux_max_u32(km);
    unsigned il = 0xFFFFFFFFu;
    if (k3 == M) il = 4 * l + 3;
    if (k2 == M) il = 4 * l + 2;
    if (k1 == M) il = 4 * l + 1;
    if (k0 == M) il = 4 * l + 0;
    return (int)redux_min_u32(il);
}

__device__ __forceinline__ void bt_step(float4 cur, const float* __restrict__ s_tr,
                                        int& tag, float* __restrict__ outrow,
                                        int l, bool addtr)
{
    if (addtr) {
        float4 tc = *reinterpret_cast<const float4*>(&s_tr[tag * TRP + 4 * l]);
        cur.x += tc.x; cur.y += tc.y; cur.z += tc.z; cur.w += tc.w;
    }
    tag = argmax128(cur, l);
    float4 r;
    r.x = (4 * l + 0 == tag) ? 1.0f : 0.0f;
    r.y = (4 * l + 1 == tag) ? 1.0f : 0.0f;
    r.z = (4 * l + 2 == tag) ? 1.0f : 0.0f;
    r.w = (4 * l + 3 == tag) ? 1.0f : 0.0f;
    reinterpret_cast<float4*>(outrow)[l] = r;
}

// ---------------------------------------------------------------------------
// Fused Viterbi: one CTA = one batch, 512 threads (16 warps, 4/SMSP).
// Thread (q, j): partial max over i in [32q, 32q+32) for tag j.
// Owner warp of quarter q is warp 4q+q: its lanes hold j in [32q, 32q+32) ==
// quarter q's i-range, so it alone combines partials, produces the quarter's
// next 32-float state slice, writes g_states, and prefetches pot.
// Sync: one full barrier (partials) + one named quarter barrier (state).
// ---------------------------------------------------------------------------
__global__ void __launch_bounds__(512, 1) crf_kernel(
    const float* __restrict__ pot,
    const float* __restrict__ trans,
    const int*   __restrict__ lens,
    float*       __restrict__ out)
{
    extern __shared__ float sm[];
    float* s_tr = sm;                        // KK*TRP transposed transitions
    float* s_pt = sm + KK * TRP;             // 2 * 4*PTR partials (ping-pong)
    float* s_st = s_pt + 2 * 4 * PTR;        // 2 * 4*32 state slices (pp)

    const int tid = threadIdx.x;
    const int w   = tid >> 5;                // warp 0..15
    const int l   = tid & 31;
    const int q   = tid >> 7;                // quarter 0..3 (i-range owner)
    const int j   = tid & 127;               // output tag
    const bool owner = ((w & 3) == q);       // warp 4q+q
    const int j_own  = 32 * q + l;           // owner lane's tag (== its i idx)

    const int b   = g_order[blockIdx.x];
    const int len = lens[b];
    const size_t base = (size_t)b * TT * KK;

    // Stage transposed transitions for the backtrace.
    for (int idx = tid; idx < KK * KK; idx += 512) {
        int row = idx >> 7, col = idx & 127;
        s_tr[col * TRP + row] = trans[idx];
    }

    // Transitions for i in [32q, 32q+32), column j -> 16 packed u64 regs.
    unsigned long long tq[16];
    #pragma unroll
    for (int m = 0; m < 8; ++m) {
        const float* r0 = trans + (size_t)(32 * q + 4 * m) * KK + j;
        tq[2 * m + 0] = pk(r0[0 * KK], r0[1 * KK]);
        tq[2 * m + 1] = pk(r0[2 * KK], r0[3 * KK]);
    }

    // Init: owner warps seed state slice, g_states row 0, and the pot ring.
    const int lm1 = len - 1;
    float xr[4];
    if (owner) {
        float s0 = pot[base + j_own];
        s_st[q * 32 + l] = s0;               // parity-0 buffer
        g_states[base + j_own] = s0;
        #pragma unroll
        for (int d = 0; d < 4; ++d) {
            int tt = (1 + d < lm1) ? (1 + d) : lm1;
            xr[d] = (len > 1) ? pot[base + (size_t)tt * KK + j_own] : 0.0f;
        }
    }
    __syncthreads();

    // ---- forward Viterbi ----
    int par = 0;
    #pragma unroll 4
    for (int t = 1; t < len; ++t) {
        // Phase A: partial max over own 32-i range (broadcast LDS.128).
        const ulonglong2* sp =
            reinterpret_cast<const ulonglong2*>(s_st + par * 128 + q * 32);
        float m0 = -FLT_MAX, m1 = -FLT_MAX, m2 = -FLT_MAX, m3 = -FLT_MAX;
        float m4 = -FLT_MAX, m5 = -FLT_MAX, m6 = -FLT_MAX, m7 = -FLT_MAX;
        #pragma unroll
        for (int m = 0; m < 8; m += 2) {
            ulonglong2 sa = sp[m];
            float2 u0 = unpk(addx2(sa.x, tq[2 * m + 0]));
            float2 u1 = unpk(addx2(sa.y, tq[2 * m + 1]));
            m0 = fmaxf(m0, u0.x);
            m1 = fmaxf(m1, u0.y);
            m2 = fmaxf(m2, u1.x);
            m3 = fmaxf(m3, u1.y);
            ulonglong2 sb = sp[m + 1];
            float2 u2 = unpk(addx2(sb.x, tq[2 * m + 2]));
            float2 u3 = unpk(addx2(sb.y, tq[2 * m + 3]));
            m4 = fmaxf(m4, u2.x);
            m5 = fmaxf(m5, u2.y);
            m6 = fmaxf(m6, u3.x);
            m7 = fmaxf(m7, u3.y);
        }
        float pm = fmaxf(fmaxf(fmaxf(m0, m1), fmaxf(m2, m3)),
                         fmaxf(fmaxf(m4, m5), fmaxf(m6, m7)));
        s_pt[par * 4 * PTR + q * PTR + j] = pm;
        __syncthreads();

        // Phase B: owner warps combine + publish next state slice.
        if (owner) {
            float x = xr[(t - 1) & 3];
            int tn = (t + 4 < lm1) ? (t + 4) : lm1;
            xr[(t - 1) & 3] = pot[base + (size_t)tn * KK + j_own];
            const float* pr = s_pt + par * 4 * PTR;
            float p0 = pr[0 * PTR + j_own];
            float p1 = pr[1 * PTR + j_own];
            float p2 = pr[2 * PTR + j_own];
            float p3 = pr[3 * PTR + j_own];
            float ns = x + fmaxf(fmaxf(p0, p1), fmaxf(p2, p3));
            s_st[(par ^ 1) * 128 + q * 32 + l] = ns;
            g_states[base + (size_t)t * KK + j_own] = ns;
        }
        bar_named(1 + q, 128);               // quarter's state slice ready
        par ^= 1;
    }
    __syncthreads();

    // ---- epilogue: warp 0 backtraces; warps 1-15 write tag-0 rows >= len ----
    if (w != 0) {
        const int total = (TT - len) * 32;
        for (int idx = (w - 1) * 32 + l; idx < total; idx += 480) {
            int r = len + (idx >> 5);
            int c = idx & 31;
            float4 v = make_float4(c == 0 ? 1.0f : 0.0f, 0.0f, 0.0f, 0.0f);
            reinterpret_cast<float4*>(out + base + (size_t)r * KK)[c] = v;
        }
        return;
    }

    auto LDst = [&](int t) -> float4 {
        if (t < 0) return make_float4(0.f, 0.f, 0.f, 0.f);
        return reinterpret_cast<const float4*>(&g_states[base + (size_t)t * KK])[l];
    };
    float* const ob = out + base;

    int tag = 0;
    float4 c0 = LDst(len - 1);
    int t = len - 2;
    float4 p0 = LDst(t), p1 = LDst(t - 1), p2 = LDst(t - 2), p3 = LDst(t - 3);

    bt_step(c0, s_tr, tag, ob + (size_t)(len - 1) * KK, l, false);

    while (t >= 3) {
        bt_step(p0, s_tr, tag, ob + (size_t)(t    ) * KK, l, true);  p0 = LDst(t - 4);
        bt_step(p1, s_tr, tag, ob + (size_t)(t - 1) * KK, l, true);  p1 = LDst(t - 5);
        bt_step(p2, s_tr, tag, ob + (size_t)(t - 2) * KK, l, true);  p2 = LDst(t - 6);
        bt_step(p3, s_tr, tag, ob + (size_t)(t - 3) * KK, l, true);  p3 = LDst(t - 7);
        t -= 4;
    }
    if (t >= 0) bt_step(p0, s_tr, tag, ob + (size_t)(t    ) * KK, l, true);
    if (t >= 1) bt_step(p1, s_tr, tag, ob + (size_t)(t - 1) * KK, l, true);
    if (t >= 2) bt_step(p2, s_tr, tag, ob + (size_t)(t - 2) * KK, l, true);
}

// ---------------------------------------------------------------------------
extern "C" void kernel_launch(void* const* d_in, const int* in_sizes, int n_in,
                              void* d_out, int out_size)
{
    const float* pot   = (const float*)d_in[0];   // (B,T,K) f32
    const float* trans = (const float*)d_in[1];   // (K,K)   f32
    const int*   lens  = (const int*)  d_in[2];   // (B,)    i32
    float* out = (float*)d_out;                   // (B,T,K) f32

    const int smem = (KK * TRP + 2 * 4 * PTR + 2 * 128) * (int)sizeof(float);
    cudaFuncSetAttribute(crf_kernel, cudaFuncAttributeMaxDynamicSharedMemorySize, smem);

    order_kernel<<<1, BB>>>(lens);
    crf_kernel<<<BB, 512, smem>>>(pot, trans, lens, out);
}

// round 11
// speedup vs baseline: 1.1208x; 1.1208x over previous
#include <cuda_runtime.h>
#include <cfloat>

#define BB 256
#define TT 512
#define KK 128
#define TRP 132   // padded transposed-transitions row stride (floats)

// Scratch (__device__ globals only — no runtime allocation)
__device__ float g_states[(size_t)BB * TT * KK];   // 64 MiB Viterbi states
__device__ int   g_order[BB];                      // bid -> batch

// ---------------------------------------------------------------------------
// Rank batches by descending length; bid r (r<148) and bid 403-r land on the
// same SM under the classic placement: long batches pair with short ones.
// ---------------------------------------------------------------------------
__global__ void order_kernel(const int* __restrict__ lens)
{
    __shared__ int sl[BB];
    const int b = threadIdx.x;
    sl[b] = lens[b];
    __syncthreads();
    const int L = sl[b];
    int r = 0;
    #pragma unroll 8
    for (int i = 0; i < BB; ++i) {
        int Li = sl[i];
        r += (Li > L) || (Li == L && i < b);
    }
    g_order[(r < 148) ? r : (403 - r)] = b;
}

// ---------------------------------------------------------------------------
// Packed f32x2 add (sm_103a). max.f32x2 does not exist; FMNMX stays scalar.
// ---------------------------------------------------------------------------
__device__ __forceinline__ unsigned long long addx2(unsigned long long a,
                                                    unsigned long long b) {
    unsigned long long r;
    asm("add.rn.f32x2 %0, %1, %2;" : "=l"(r) : "l"(a), "l"(b));
    return r;
}
__device__ __forceinline__ float2 unpk(unsigned long long v) {
    float2 r;
    asm("mov.b64 {%0, %1}, %2;" : "=f"(r.x), "=f"(r.y) : "l"(v));
    return r;
}
__device__ __forceinline__ unsigned long long pk(float lo, float hi) {
    unsigned long long r;
    asm("mov.b64 %0, {%1, %2};" : "=l"(r) : "f"(lo), "f"(hi));
    return r;
}

// ---------------------------------------------------------------------------
// Backtrace helpers (warp-uniform argmax, first-index tie-break)
// ---------------------------------------------------------------------------
__device__ __forceinline__ unsigned redux_max_u32(unsigned v) {
    unsigned r;
    asm("redux.sync.max.u32 %0, %1, 0xffffffff;" : "=r"(r) : "r"(v));
    return r;
}
__device__ __forceinline__ unsigned redux_min_u32(unsigned v) {
    unsigned r;
    asm("redux.sync.min.u32 %0, %1, 0xffffffff;" : "=r"(r) : "r"(v));
    return r;
}
__device__ __forceinline__ unsigned fkey(float f) {
    unsigned u = __float_as_uint(f);
    return u ^ ((unsigned)((int)u >> 31) | 0x80000000u);
}
__device__ __forceinline__ int argmax128(float4 v, int l)
{
    unsigned k0 = fkey(v.x), k1 = fkey(v.y), k2 = fkey(v.z), k3 = fkey(v.w);
    unsigned km = max(max(k0, k1), max(k2, k3));
    unsigned M  = redux_max_u32(km);
    unsigned il = 0xFFFFFFFFu;
    if (k3 == M) il = 4 * l + 3;
    if (k2 == M) il = 4 * l + 2;
    if (k1 == M) il = 4 * l + 1;
    if (k0 == M) il = 4 * l + 0;
    return (int)redux_min_u32(il);
}

__device__ __forceinline__ void bt_step(float4 cur, const float* __restrict__ s_tr,
                                        int& tag, float* __restrict__ outrow,
                                        int l, bool addtr)
{
    if (addtr) {
        float4 tc = *reinterpret_cast<const float4*>(&s_tr[tag * TRP + 4 * l]);
        cur.x += tc.x; cur.y += tc.y; cur.z += tc.z; cur.w += tc.w;
    }
    tag = argmax128(cur, l);
    float4 r;
    r.x = (4 * l + 0 == tag) ? 1.0f : 0.0f;
    r.y = (4 * l + 1 == tag) ? 1.0f : 0.0f;
    r.z = (4 * l + 2 == tag) ? 1.0f : 0.0f;
    r.w = (4 * l + 3 == tag) ? 1.0f : 0.0f;
    reinterpret_cast<float4*>(outrow)[l] = r;
}

// ---------------------------------------------------------------------------
// Fused Viterbi: one CTA = one batch, 128 threads. Thread j owns output tag j;
// full transitions column j in packed f32x2 registers. Depth-4 prefetch ring
// keeps the pot load off the per-step critical path. The g_states STG is
// issued AFTER the step barrier so the barrier never waits on its L2 drain.
// ---------------------------------------------------------------------------
__global__ void __launch_bounds__(128, 2) crf_kernel(
    const float* __restrict__ pot,
    const float* __restrict__ trans,
    const int*   __restrict__ lens,
    float*       __restrict__ out)
{
    extern __shared__ float sm[];
    float* s_tr = sm;                  // KK*TRP: transposed transitions
    float* s_st = sm + KK * TRP;       // 2*KK ping-pong state

    const int j = threadIdx.x;
    const int b = g_order[blockIdx.x];
    const int len = lens[b];
    const size_t base = (size_t)b * TT * KK;

    // Transitions column j -> 64 packed u64 registers; also stage the
    // transposed copy in smem for the backtrace.
    unsigned long long ad[64];
    #pragma unroll
    for (int q = 0; q < 32; ++q) {
        float v0 = trans[(4 * q + 0) * KK + j];
        float v1 = trans[(4 * q + 1) * KK + j];
        float v2 = trans[(4 * q + 2) * KK + j];
        float v3 = trans[(4 * q + 3) * KK + j];
        ad[2 * q + 0] = pk(v0, v1);
        ad[2 * q + 1] = pk(v2, v3);
        *reinterpret_cast<float4*>(&s_tr[j * TRP + 4 * q]) =
            make_float4(v0, v1, v2, v3);
    }

    float s0 = pot[base + j];
    s_st[j] = s0;
    g_states[base + j] = s0;

    // Depth-4 prefetch ring for the emission potentials.
    const int lm1 = len - 1;
    float xr[4];
    #pragma unroll
    for (int d = 0; d < 4; ++d) {
        int tt = (1 + d < lm1) ? (1 + d) : lm1;
        xr[d] = (len > 1) ? pot[base + (size_t)tt * KK + j] : 0.0f;
    }
    __syncthreads();

    // ---- forward Viterbi ----
    int p = 0;
    #pragma unroll 4
    for (int t = 1; t < len; ++t) {
        float x = xr[(t - 1) & 3];
        int tn = (t + 4 < lm1) ? (t + 4) : lm1;
        xr[(t - 1) & 3] = pot[base + (size_t)tn * KK + j];  // prefetch t+4

        const ulonglong2* sp = reinterpret_cast<const ulonglong2*>(s_st + p * KK);
        float m0 = -FLT_MAX, m1 = -FLT_MAX, m2 = -FLT_MAX, m3 = -FLT_MAX;
        float m4 = -FLT_MAX, m5 = -FLT_MAX, m6 = -FLT_MAX, m7 = -FLT_MAX;
        #pragma unroll
        for (int q = 0; q < 32; q += 2) {
            ulonglong2 sa = sp[q];                          // broadcast LDS.128
            float2 u0 = unpk(addx2(sa.x, ad[2 * q + 0]));
            float2 u1 = unpk(addx2(sa.y, ad[2 * q + 1]));
            m0 = fmaxf(m0, u0.x);
            m1 = fmaxf(m1, u0.y);
            m2 = fmaxf(m2, u1.x);
            m3 = fmaxf(m3, u1.y);
            ulonglong2 sb = sp[q + 1];
            float2 u2 = unpk(addx2(sb.x, ad[2 * q + 2]));
            float2 u3 = unpk(addx2(sb.y, ad[2 * q + 3]));
            m4 = fmaxf(m4, u2.x);
            m5 = fmaxf(m5, u2.y);
            m6 = fmaxf(m6, u3.x);
            m7 = fmaxf(m7, u3.y);
        }
        float ma = fmaxf(fmaxf(m0, m1), fmaxf(m2, m3));
        float mb = fmaxf(fmaxf(m4, m5), fmaxf(m6, m7));
        float ns = x + fmaxf(ma, mb);

        s_st[(p ^ 1) * KK + j] = ns;
        __syncthreads();
        // STG issued AFTER the barrier: it has the whole next step to reach
        // L2, so no barrier ever stalls on its drain. Visibility for the
        // epilogue is guaranteed by the post-loop __syncthreads.
        g_states[base + (size_t)t * KK + j] = ns;
        p ^= 1;
    }
    __syncthreads();   // make the final rows visible to the backtrace warp

    // ---- epilogue: warp 0 backtraces; warps 1-3 write tag-0 rows >= len ----
    const int w = j >> 5;
    const int l = j & 31;

    if (w != 0) {
        const int total = (TT - len) * 32;
        for (int idx = (w - 1) * 32 + l; idx < total; idx += 96) {
            int r = len + (idx >> 5);
            int c = idx & 31;
            float4 v = make_float4(c == 0 ? 1.0f : 0.0f, 0.0f, 0.0f, 0.0f);
            reinterpret_cast<float4*>(out + base + (size_t)r * KK)[c] = v;
        }
        return;
    }

    auto LDst = [&](int t) -> float4 {
        if (t < 0) return make_float4(0.f, 0.f, 0.f, 0.f);
        return reinterpret_cast<const float4*>(&g_states[base + (size_t)t * KK])[l];
    };
    float* const ob = out + base;

    int tag = 0;
    float4 c0 = LDst(len - 1);
    int t = len - 2;
    float4 p0 = LDst(t), p1 = LDst(t - 1), p2 = LDst(t - 2), p3 = LDst(t - 3);

    bt_step(c0, s_tr, tag, ob + (size_t)(len - 1) * KK, l, false);

    while (t >= 3) {
        bt_step(p0, s_tr, tag, ob + (size_t)(t    ) * KK, l, true);  p0 = LDst(t - 4);
        bt_step(p1, s_tr, tag, ob + (size_t)(t - 1) * KK, l, true);  p1 = LDst(t - 5);
        bt_step(p2, s_tr, tag, ob + (size_t)(t - 2) * KK, l, true);  p2 = LDst(t - 6);
        bt_step(p3, s_tr, tag, ob + (size_t)(t - 3) * KK, l, true);  p3 = LDst(t - 7);
        t -= 4;
    }
    if (t >= 0) bt_step(p0, s_tr, tag, ob + (size_t)(t    ) * KK, l, true);
    if (t >= 1) bt_step(p1, s_tr, tag, ob + (size_t)(t - 1) * KK, l, true);
    if (t >= 2) bt_step(p2, s_tr, tag, ob + (size_t)(t - 2) * KK, l, true);
}

// ---------------------------------------------------------------------------
extern "C" void kernel_launch(void* const* d_in, const int* in_sizes, int n_in,
                              void* d_out, int out_size)
{
    const float* pot   = (const float*)d_in[0];   // (B,T,K) f32
    const float* trans = (const float*)d_in[1];   // (K,K)   f32
    const int*   lens  = (const int*)  d_in[2];   // (B,)    i32
    float* out = (float*)d_out;                   // (B,T,K) f32

    const int smem = (KK * TRP + 2 * KK) * (int)sizeof(float);   // 68,608 B
    cudaFuncSetAttribute(crf_kernel, cudaFuncAttributeMaxDynamicSharedMemorySize, smem);

    order_kernel<<<1, BB>>>(lens);
    crf_kernel<<<BB, 128, smem>>>(pot, trans, lens, out);
}

// round 12
// speedup vs baseline: 1.2527x; 1.1177x over previous
#include <cuda_runtime.h>
#include <cfloat>

#define BB 256
#define TT 512
#define KK 128
#define TRP 132   // padded transposed-transitions row stride (floats)

// Scratch (__device__ globals only — no runtime allocation)
__device__ float g_states[(size_t)BB * TT * KK];   // 64 MiB Viterbi states
__device__ int   g_order[BB];                      // bid -> batch

// ---------------------------------------------------------------------------
// Rank batches by descending length; bid r (r<148) and bid 403-r land on the
// same SM under the classic placement: long batches pair with short ones.
// ---------------------------------------------------------------------------
__global__ void order_kernel(const int* __restrict__ lens)
{
    __shared__ int sl[BB];
    const int b = threadIdx.x;
    sl[b] = lens[b];
    __syncthreads();
    const int L = sl[b];
    int r = 0;
    #pragma unroll 8
    for (int i = 0; i < BB; ++i) {
        int Li = sl[i];
        r += (Li > L) || (Li == L && i < b);
    }
    g_order[(r < 148) ? r : (403 - r)] = b;
}

// ---------------------------------------------------------------------------
// Packed f32x2 add (sm_103a). max.f32x2 does not exist; FMNMX stays scalar.
// ---------------------------------------------------------------------------
__device__ __forceinline__ unsigned long long addx2(unsigned long long a,
                                                    unsigned long long b) {
    unsigned long long r;
    asm("add.rn.f32x2 %0, %1, %2;" : "=l"(r) : "l"(a), "l"(b));
    return r;
}
__device__ __forceinline__ float2 unpk(unsigned long long v) {
    float2 r;
    asm("mov.b64 {%0, %1}, %2;" : "=f"(r.x), "=f"(r.y) : "l"(v));
    return r;
}
__device__ __forceinline__ unsigned long long pk(float lo, float hi) {
    unsigned long long r;
    asm("mov.b64 %0, {%1, %2};" : "=l"(r) : "f"(lo), "f"(hi));
    return r;
}

// ---------------------------------------------------------------------------
// Backtrace helpers (warp-uniform argmax, first-index tie-break)
// ---------------------------------------------------------------------------
__device__ __forceinline__ unsigned redux_max_u32(unsigned v) {
    unsigned r;
    asm("redux.sync.max.u32 %0, %1, 0xffffffff;" : "=r"(r) : "r"(v));
    return r;
}
__device__ __forceinline__ unsigned redux_min_u32(unsigned v) {
    unsigned r;
    asm("redux.sync.min.u32 %0, %1, 0xffffffff;" : "=r"(r) : "r"(v));
    return r;
}
__device__ __forceinline__ unsigned fkey(float f) {
    unsigned u = __float_as_uint(f);
    return u ^ ((unsigned)((int)u >> 31) | 0x80000000u);
}
__device__ __forceinline__ int argmax128(float4 v, int l)
{
    unsigned k0 = fkey(v.x), k1 = fkey(v.y), k2 = fkey(v.z), k3 = fkey(v.w);
    unsigned km = max(max(k0, k1), max(k2, k3));
    unsigned M  = redux_max_u32(km);
    unsigned il = 0xFFFFFFFFu;
    if (k3 == M) il = 4 * l + 3;
    if (k2 == M) il = 4 * l + 2;
    if (k1 == M) il = 4 * l + 1;
    if (k0 == M) il = 4 * l + 0;
    return (int)redux_min_u32(il);
}

__device__ __forceinline__ void bt_step(float4 cur, const float* __restrict__ s_tr,
                                        int& tag, float* __restrict__ outrow,
                                        int l, bool addtr)
{
    if (addtr) {
        float4 tc = *reinterpret_cast<const float4*>(&s_tr[tag * TRP + 4 * l]);
        cur.x += tc.x; cur.y += tc.y; cur.z += tc.z; cur.w += tc.w;
    }
    tag = argmax128(cur, l);
    float4 r;
    r.x = (4 * l + 0 == tag) ? 1.0f : 0.0f;
    r.y = (4 * l + 1 == tag) ? 1.0f : 0.0f;
    r.z = (4 * l + 2 == tag) ? 1.0f : 0.0f;
    r.w = (4 * l + 3 == tag) ? 1.0f : 0.0f;
    reinterpret_cast<float4*>(outrow)[l] = r;
}

// ---------------------------------------------------------------------------
// Fused Viterbi: one CTA = one batch, 128 threads. Thread j owns output tag j;
// full transitions column j in packed f32x2 registers. Depth-8 prefetch ring
// for pot; inner loop loads 4x LDS.128 per group to keep >=4 loads in flight.
// ---------------------------------------------------------------------------
__global__ void __launch_bounds__(128, 2) crf_kernel(
    const float* __restrict__ pot,
    const float* __restrict__ trans,
    const int*   __restrict__ lens,
    float*       __restrict__ out)
{
    extern __shared__ float sm[];
    float* s_tr = sm;                  // KK*TRP: transposed transitions
    float* s_st = sm + KK * TRP;       // 2*KK ping-pong state

    const int j = threadIdx.x;
    const int b = g_order[blockIdx.x];
    const int len = lens[b];
    const size_t base = (size_t)b * TT * KK;

    // Transitions column j -> 64 packed u64 registers; also stage the
    // transposed copy in smem for the backtrace.
    unsigned long long ad[64];
    #pragma unroll
    for (int q = 0; q < 32; ++q) {
        float v0 = trans[(4 * q + 0) * KK + j];
        float v1 = trans[(4 * q + 1) * KK + j];
        float v2 = trans[(4 * q + 2) * KK + j];
        float v3 = trans[(4 * q + 3) * KK + j];
        ad[2 * q + 0] = pk(v0, v1);
        ad[2 * q + 1] = pk(v2, v3);
        *reinterpret_cast<float4*>(&s_tr[j * TRP + 4 * q]) =
            make_float4(v0, v1, v2, v3);
    }

    float s0 = pot[base + j];
    s_st[j] = s0;
    g_states[base + j] = s0;

    // Depth-8 prefetch ring for the emission potentials.
    const int lm1 = len - 1;
    float xr[8];
    #pragma unroll
    for (int d = 0; d < 8; ++d) {
        int tt = (1 + d < lm1) ? (1 + d) : lm1;
        xr[d] = (len > 1) ? pot[base + (size_t)tt * KK + j] : 0.0f;
    }
    __syncthreads();

    // ---- forward Viterbi ----
    int p = 0;
    #pragma unroll 4
    for (int t = 1; t < len; ++t) {
        float x = xr[(t - 1) & 7];
        int tn = (t + 8 < lm1) ? (t + 8) : lm1;
        xr[(t - 1) & 7] = pot[base + (size_t)tn * KK + j];  // prefetch t+8

        const ulonglong2* sp = reinterpret_cast<const ulonglong2*>(s_st + p * KK);
        float m0 = -FLT_MAX, m1 = -FLT_MAX, m2 = -FLT_MAX, m3 = -FLT_MAX;
        float m4 = -FLT_MAX, m5 = -FLT_MAX, m6 = -FLT_MAX, m7 = -FLT_MAX;
        #pragma unroll
        for (int g = 0; g < 8; ++g) {
            // 4 LDS.128 batched up front: >=4 loads in flight per group.
            ulonglong2 s0v = sp[4 * g + 0];
            ulonglong2 s1v = sp[4 * g + 1];
            ulonglong2 s2v = sp[4 * g + 2];
            ulonglong2 s3v = sp[4 * g + 3];
            float2 u0 = unpk(addx2(s0v.x, ad[8 * g + 0]));
            float2 u1 = unpk(addx2(s0v.y, ad[8 * g + 1]));
            float2 u2 = unpk(addx2(s1v.x, ad[8 * g + 2]));
            float2 u3 = unpk(addx2(s1v.y, ad[8 * g + 3]));
            m0 = fmaxf(m0, u0.x);
            m1 = fmaxf(m1, u0.y);
            m2 = fmaxf(m2, u1.x);
            m3 = fmaxf(m3, u1.y);
            m4 = fmaxf(m4, u2.x);
            m5 = fmaxf(m5, u2.y);
            m6 = fmaxf(m6, u3.x);
            m7 = fmaxf(m7, u3.y);
            float2 u4 = unpk(addx2(s2v.x, ad[8 * g + 4]));
            float2 u5 = unpk(addx2(s2v.y, ad[8 * g + 5]));
            float2 u6 = unpk(addx2(s3v.x, ad[8 * g + 6]));
            float2 u7 = unpk(addx2(s3v.y, ad[8 * g + 7]));
            m0 = fmaxf(m0, u4.x);
            m1 = fmaxf(m1, u4.y);
            m2 = fmaxf(m2, u5.x);
            m3 = fmaxf(m3, u5.y);
            m4 = fmaxf(m4, u6.x);
            m5 = fmaxf(m5, u6.y);
            m6 = fmaxf(m6, u7.x);
            m7 = fmaxf(m7, u7.y);
        }
        float ma = fmaxf(fmaxf(m0, m1), fmaxf(m2, m3));
        float mb = fmaxf(fmaxf(m4, m5), fmaxf(m6, m7));
        float ns = x + fmaxf(ma, mb);

        s_st[(p ^ 1) * KK + j] = ns;
        g_states[base + (size_t)t * KK + j] = ns;
        __syncthreads();
        p ^= 1;
    }

    // ---- epilogue: warp 0 backtraces; warps 1-3 write tag-0 rows >= len ----
    const int w = j >> 5;
    const int l = j & 31;

    if (w != 0) {
        const int total = (TT - len) * 32;
        for (int idx = (w - 1) * 32 + l; idx < total; idx += 96) {
            int r = len + (idx >> 5);
            int c = idx & 31;
            float4 v = make_float4(c == 0 ? 1.0f : 0.0f, 0.0f, 0.0f, 0.0f);
            reinterpret_cast<float4*>(out + base + (size_t)r * KK)[c] = v;
        }
        return;
    }

    auto LDst = [&](int t) -> float4 {
        if (t < 0) return make_float4(0.f, 0.f, 0.f, 0.f);
        return reinterpret_cast<const float4*>(&g_states[base + (size_t)t * KK])[l];
    };
    float* const ob = out + base;

    int tag = 0;
    float4 c0 = LDst(len - 1);
    int t = len - 2;
    float4 p0 = LDst(t), p1 = LDst(t - 1), p2 = LDst(t - 2), p3 = LDst(t - 3);

    bt_step(c0, s_tr, tag, ob + (size_t)(len - 1) * KK, l, false);

    while (t >= 3) {
        bt_step(p0, s_tr, tag, ob + (size_t)(t    ) * KK, l, true);  p0 = LDst(t - 4);
        bt_step(p1, s_tr, tag, ob + (size_t)(t - 1) * KK, l, true);  p1 = LDst(t - 5);
        bt_step(p2, s_tr, tag, ob + (size_t)(t - 2) * KK, l, true);  p2 = LDst(t - 6);
        bt_step(p3, s_tr, tag, ob + (size_t)(t - 3) * KK, l, true);  p3 = LDst(t - 7);
        t -= 4;
    }
    if (t >= 0) bt_step(p0, s_tr, tag, ob + (size_t)(t    ) * KK, l, true);
    if (t >= 1) bt_step(p1, s_tr, tag, ob + (size_t)(t - 1) * KK, l, true);
    if (t >= 2) bt_step(p2, s_tr, tag, ob + (size_t)(t - 2) * KK, l, true);
}

// ---------------------------------------------------------------------------
extern "C" void kernel_launch(void* const* d_in, const int* in_sizes, int n_in,
                              void* d_out, int out_size)
{
    const float* pot   = (const float*)d_in[0];   // (B,T,K) f32
    const float* trans = (const float*)d_in[1];   // (K,K)   f32
    const int*   lens  = (const int*)  d_in[2];   // (B,)    i32
    float* out = (float*)d_out;                   // (B,T,K) f32

    const int smem = (KK * TRP + 2 * KK) * (int)sizeof(float);   // 68,608 B
    cudaFuncSetAttribute(crf_kernel, cudaFuncAttributeMaxDynamicSharedMemorySize, smem);

    order_kernel<<<1, BB>>>(lens);
    crf_kernel<<<BB, 128, smem>>>(pot, trans, lens, out);
}